// round 1
// baseline (speedup 1.0000x reference)
#include <cuda_runtime.h>
#include <cstddef>

// Problem constants (from reference): B=256, L=20, V=9488, S=18
#define BB 256
#define LL 20
#define VV 9488
#define SS 18
#define TLEN (LL - 1)   // 19

// Deterministic per-row partials (no device allocation allowed -> __device__ globals)
__device__ float g_psum[BB];
__device__ int   g_pcnt[BB];

// Kernel 1: one warp per batch row.
// lane j (0..18) owns padded-target position j, i.e. timestep t = j+1.
__global__ void scst_partial_kernel(const float* __restrict__ inp,
                                    const int*   __restrict__ tgt,
                                    float* __restrict__ psum,
                                    int*   __restrict__ pcnt) {
    const int b    = blockIdx.x;
    const int lane = threadIdx.x;

    // padded target value at position j: target[b][j] for j<S, else 0
    int tv = 0;
    if (lane < TLEN && lane < SS) tv = tgt[b * SS + lane];

    // inclusive cumulative zero count <= 1  <=>  popc(zero bits at positions 0..j) <= 1
    const bool     active = (lane < TLEN);
    const unsigned zball  = __ballot_sync(0xFFFFFFFFu, active && (tv == 0));

    float val = 0.0f;
    int   cnt = 0;
    if (active) {
        const unsigned incl_mask = (2u << lane) - 1u;   // bits 0..lane (lane<=18, no overflow)
        if (__popc(zball & incl_mask) <= 1) {
            cnt = 1;
            // logp = input[b, lane+1, tv]
            val = inp[(size_t)b * (size_t)(LL * VV) + (size_t)(lane + 1) * VV + tv];
        }
    }

    // warp reduction
    #pragma unroll
    for (int off = 16; off > 0; off >>= 1) {
        val += __shfl_down_sync(0xFFFFFFFFu, val, off);
        cnt += __shfl_down_sync(0xFFFFFFFFu, cnt, off);
    }
    if (lane == 0) {
        psum[b] = val;
        pcnt[b] = cnt;
    }
}

// Kernel 2: fold 256 partials, apply reward scaling, write scalar loss.
__global__ void scst_final_kernel(const float* __restrict__ psum,
                                  const int*   __restrict__ pcnt,
                                  const float* __restrict__ reward,
                                  const float* __restrict__ reward1,
                                  float* __restrict__ out) {
    const int t = threadIdx.x;   // 0..255
    float v = psum[t];
    int   c = pcnt[t];

    // intra-warp
    #pragma unroll
    for (int off = 16; off > 0; off >>= 1) {
        v += __shfl_down_sync(0xFFFFFFFFu, v, off);
        c += __shfl_down_sync(0xFFFFFFFFu, c, off);
    }

    __shared__ float sv[8];
    __shared__ int   sc[8];
    const int wid  = t >> 5;
    const int lane = t & 31;
    if (lane == 0) { sv[wid] = v; sc[wid] = c; }
    __syncthreads();

    if (wid == 0) {
        v = (lane < 8) ? sv[lane] : 0.0f;
        c = (lane < 8) ? sc[lane] : 0;
        #pragma unroll
        for (int off = 4; off > 0; off >>= 1) {
            v += __shfl_down_sync(0xFFFFFFFFu, v, off);
            c += __shfl_down_sync(0xFFFFFFFFu, c, off);
        }
        if (lane == 0) {
            float rd = reward[0] - reward1[0];
            if (rd < 1.0f) rd = 1.0f;
            out[0] = -(v / (float)c) * rd;
        }
    }
}

extern "C" void kernel_launch(void* const* d_in, const int* in_sizes, int n_in,
                              void* d_out, int out_size) {
    const float* inp     = (const float*)d_in[0];   // [B, L, V] f32
    const int*   tgt     = (const int*)  d_in[1];   // [B, S]    i32
    const float* reward  = (const float*)d_in[2];   // [1]       f32
    const float* reward1 = (const float*)d_in[3];   // [1]       f32
    float*       out     = (float*)d_out;           // [1]       f32

    float* psum; cudaGetSymbolAddress((void**)&psum, g_psum);
    int*   pcnt; cudaGetSymbolAddress((void**)&pcnt, g_pcnt);

    scst_partial_kernel<<<BB, 32>>>(inp, tgt, psum, pcnt);
    scst_final_kernel<<<1, 256>>>(psum, pcnt, reward, reward1, out);
}